// round 2
// baseline (speedup 1.0000x reference)
#include <cuda_runtime.h>

// y = conv2d(x[1,512,512,16], w[3,3,16,64], SAME) ; pot = y + old
// spike = pot >= 1 ; new_pot = spike ? 0 : pot
// d_out layout: [spikes 512*512*64][new_pot 512*512*64]

#define HH 512
#define WW 512
#define CIN 16
#define COUT 64
#define TH 16
#define TW 16

#define WELEMS (9 * 16 * 64)            /* 9216 weight floats */
#define INPITCHX 20                     /* padded x-pitch (floats): conflict-free */
#define INPITCHY ((TW + 2) * INPITCHX)  /* 18*20 = 360 */
#define INELEMS ((TH + 2) * INPITCHY)   /* 6480 */
#define SMEM_BYTES ((WELEMS + INELEMS) * 4) /* 62784 B */

__device__ __forceinline__ unsigned long long pack2(float x) {
    unsigned long long v;
    asm("mov.b64 %0, {%1, %1};" : "=l"(v) : "f"(x));
    return v;
}
__device__ __forceinline__ void ffma2(unsigned long long& d,
                                      unsigned long long a,
                                      unsigned long long b) {
    asm("fma.rn.f32x2 %0, %1, %2, %0;" : "+l"(d) : "l"(a), "l"(b));
}
__device__ __forceinline__ float2 unpack2(unsigned long long v) {
    float2 r;
    asm("mov.b64 {%0, %1}, %2;" : "=f"(r.x), "=f"(r.y) : "l"(v));
    return r;
}

__global__ void __launch_bounds__(256, 2)
snn_conv_kernel(const float* __restrict__ in, const float* __restrict__ wt,
                const float* __restrict__ oldp,
                float* __restrict__ out_spk, float* __restrict__ out_pot) {
    extern __shared__ float smem[];
    float* s_w  = smem;            // [9][16][64]
    float* s_in = smem + WELEMS;   // [18][18 (pitch 20)][16]

    const int tid = threadIdx.x;
    const int x0 = blockIdx.x * TW;
    const int y0 = blockIdx.y * TH;

    // ---- stage weights ----
    {
        const float4* src = (const float4*)wt;
        float4* dst = (float4*)s_w;
        #pragma unroll
        for (int i = tid; i < WELEMS / 4; i += 256) dst[i] = src[i];
    }
    // ---- stage input tile + zero halo ----
    for (int i = tid; i < 18 * 18 * 4; i += 256) {
        int v = i & 3;
        int xy = i >> 2;
        int sy = xy / 18;
        int sx = xy - sy * 18;
        int gy = y0 + sy - 1;
        int gx = x0 + sx - 1;
        float4 val = make_float4(0.f, 0.f, 0.f, 0.f);
        if ((unsigned)gy < HH && (unsigned)gx < WW)
            val = *(const float4*)(in + (gy * WW + gx) * CIN + v * 4);
        *(float4*)(s_in + sy * INPITCHY + sx * INPITCHX + v * 4) = val;
    }
    __syncthreads();

    // thread -> 16 output channels (cg*16..+15) x 4 y-adjacent pixels
    const int cg  = tid & 3;         // 4 consecutive lanes share cg -> smem broadcast
    const int pg  = tid >> 2;        // 0..63
    const int px  = pg & 15;
    const int py0 = (pg >> 4) * 4;   // y-block of 4

    unsigned long long acc[4][8];    // [pixel][cout-pair]
    #pragma unroll
    for (int p = 0; p < 4; p++)
        #pragma unroll
        for (int j = 0; j < 8; j++) acc[p][j] = 0ull;

    #pragma unroll 1
    for (int ci4 = 0; ci4 < 4; ci4++) {      // groups of 4 input channels
        #pragma unroll 1
        for (int dx = 0; dx < 3; dx++) {
            // 6-row input column (4 px + 2 halo), 4 ci at once; reused across dy
            const float* ibase = s_in + py0 * INPITCHY + (px + dx) * INPITCHX + ci4 * 4;
            float4 col[6];
            #pragma unroll
            for (int i = 0; i < 6; i++)
                col[i] = *(const float4*)(ibase + i * INPITCHY);

            #pragma unroll
            for (int dy = 0; dy < 3; dy++) {
                const float* wb = s_w + ((dy * 3 + dx) * 16 + ci4 * 4) * 64 + cg * 16;
                #pragma unroll
                for (int c = 0; c < 4; c++) {
                    ulonglong2 wA = *(const ulonglong2*)(wb + c * 64);
                    ulonglong2 wB = *(const ulonglong2*)(wb + c * 64 + 4);
                    ulonglong2 wC = *(const ulonglong2*)(wb + c * 64 + 8);
                    ulonglong2 wD = *(const ulonglong2*)(wb + c * 64 + 12);
                    #pragma unroll
                    for (int p = 0; p < 4; p++) {
                        float xs = ((const float*)&col[dy + p])[c];
                        unsigned long long xv = pack2(xs);
                        ffma2(acc[p][0], xv, wA.x);
                        ffma2(acc[p][1], xv, wA.y);
                        ffma2(acc[p][2], xv, wB.x);
                        ffma2(acc[p][3], xv, wB.y);
                        ffma2(acc[p][4], xv, wC.x);
                        ffma2(acc[p][5], xv, wC.y);
                        ffma2(acc[p][6], xv, wD.x);
                        ffma2(acc[p][7], xv, wD.y);
                    }
                }
            }
        }
    }

    // ---- epilogue: +old potential, threshold, reset, store both ----
    const int gx = x0 + px;
    #pragma unroll
    for (int p = 0; p < 4; p++) {
        int gy = y0 + py0 + p;
        int base = (gy * WW + gx) * COUT + cg * 16;
        #pragma unroll
        for (int h = 0; h < 4; h++) {      // 4 float4 chunks of the 16 couts
            float4 o = *(const float4*)(oldp + base + h * 4);
            float2 a0 = unpack2(acc[p][h * 2]);
            float2 a1 = unpack2(acc[p][h * 2 + 1]);
            float v0 = a0.x + o.x, v1 = a0.y + o.y;
            float v2 = a1.x + o.z, v3 = a1.y + o.w;
            bool f0 = v0 >= 1.0f, f1 = v1 >= 1.0f, f2 = v2 >= 1.0f, f3 = v3 >= 1.0f;
            *(float4*)(out_spk + base + h * 4) =
                make_float4(f0 ? 1.f : 0.f, f1 ? 1.f : 0.f,
                            f2 ? 1.f : 0.f, f3 ? 1.f : 0.f);
            *(float4*)(out_pot + base + h * 4) =
                make_float4(f0 ? 0.f : v0, f1 ? 0.f : v1,
                            f2 ? 0.f : v2, f3 ? 0.f : v3);
        }
    }
}

extern "C" void kernel_launch(void* const* d_in, const int* in_sizes, int n_in,
                              void* d_out, int out_size) {
    const float* in   = (const float*)d_in[0];   // [1,512,512,16]
    const float* wt   = (const float*)d_in[1];   // [3,3,16,64]
    const float* oldp = (const float*)d_in[2];   // [1,512,512,64]
    float* spk = (float*)d_out;
    float* pot = (float*)d_out + in_sizes[2];

    cudaFuncSetAttribute(snn_conv_kernel,
                         cudaFuncAttributeMaxDynamicSharedMemorySize, SMEM_BYTES);

    dim3 grid(WW / TW, HH / TH);
    snn_conv_kernel<<<grid, 256, SMEM_BYTES>>>(in, wt, oldp, spk, pot);
}

// round 3
// speedup vs baseline: 1.2041x; 1.2041x over previous
#include <cuda_runtime.h>

// y = conv2d(x[1,512,512,16], w[3,3,16,64], SAME); pot = y + old
// spike = pot >= 1; new_pot = spike ? 0 : pot
// d_out: [spikes 512*512*64][new_pot 512*512*64]

#define HH 512
#define WW 512
#define CIN 16
#define COUT 64
#define TH 16
#define TW 16

#define WELEMS (9 * 16 * 64)       /* 9216 floats */
#define IPX 19                     /* x-pitch (16 ch + 3 pad) -> conflict-free */
#define IPY (18 * IPX)             /* 342 */
#define INELEMS (18 * IPY)         /* 6156 */
#define SMEM_BYTES ((WELEMS + INELEMS) * 4)  /* 61488 B */

__device__ __forceinline__ unsigned long long pack2(float x) {
    unsigned long long v;
    asm("mov.b64 %0, {%1, %1};" : "=l"(v) : "f"(x));
    return v;
}
__device__ __forceinline__ void ffma2(unsigned long long& d,
                                      unsigned long long a,
                                      unsigned long long b) {
    asm("fma.rn.f32x2 %0, %1, %2, %0;" : "+l"(d) : "l"(a), "l"(b));
}
__device__ __forceinline__ float2 unpack2(unsigned long long v) {
    float2 r;
    asm("mov.b64 {%0, %1}, %2;" : "=f"(r.x), "=f"(r.y) : "l"(v));
    return r;
}

__global__ void __launch_bounds__(256, 2)
snn_conv_kernel(const float* __restrict__ in, const float* __restrict__ wt,
                const float* __restrict__ oldp,
                float* __restrict__ out_spk, float* __restrict__ out_pot) {
    extern __shared__ float smem[];
    float* s_w  = smem;            // [9][16][64]
    float* s_in = smem + WELEMS;   // [18 rows][18 x (pitch 19)][16 ch]

    const int tid = threadIdx.x;
    const int x0 = blockIdx.x * TW;
    const int y0 = blockIdx.y * TH;

    // ---- stage weights (float4, aligned) ----
    {
        const float4* src = (const float4*)wt;
        float4* dst = (float4*)s_w;
        #pragma unroll
        for (int i = tid; i < WELEMS / 4; i += 256) dst[i] = src[i];
    }
    // ---- stage input tile + zero halo (scalar STS; pitch 19 unaligned for v4) ----
    for (int i = tid; i < 18 * 18; i += 256) {
        int sy = i / 18;
        int sx = i - sy * 18;
        int gy = y0 + sy - 1;
        int gx = x0 + sx - 1;
        float4 v0, v1, v2, v3;
        if ((unsigned)gy < HH && (unsigned)gx < WW) {
            const float4* g = (const float4*)(in + (gy * WW + gx) * CIN);
            v0 = g[0]; v1 = g[1]; v2 = g[2]; v3 = g[3];
        } else {
            v0 = v1 = v2 = v3 = make_float4(0.f, 0.f, 0.f, 0.f);
        }
        float* d = s_in + sy * IPY + sx * IPX;
        d[0]=v0.x; d[1]=v0.y; d[2]=v0.z; d[3]=v0.w;
        d[4]=v1.x; d[5]=v1.y; d[6]=v1.z; d[7]=v1.w;
        d[8]=v2.x; d[9]=v2.y; d[10]=v2.z; d[11]=v2.w;
        d[12]=v3.x; d[13]=v3.y; d[14]=v3.z; d[15]=v3.w;
    }
    __syncthreads();

    // warp -> 8 output channels (uniform across warp => smem weight broadcast)
    // lane -> 8-tall y-column of pixels at fixed x
    const int warp = tid >> 5;
    const int lane = tid & 31;
    const int cout0 = warp * 8;
    const int px  = lane & 15;
    const int py0 = (lane >> 4) * 8;

    unsigned long long acc[8][4];   // [pixel][cout-pair]
    #pragma unroll
    for (int p = 0; p < 8; p++)
        #pragma unroll
        for (int j = 0; j < 4; j++) acc[p][j] = 0ull;

    #pragma unroll 1
    for (int ci = 0; ci < 16; ci++) {
        #pragma unroll 1
        for (int dx = 0; dx < 3; dx++) {
            // 10-row input column (8 px + 2 halo), packed once, reused over dy
            const float* ib = s_in + py0 * IPY + (px + dx) * IPX + ci;
            unsigned long long xv[10];
            #pragma unroll
            for (int i = 0; i < 10; i++) xv[i] = pack2(ib[i * IPY]);

            #pragma unroll
            for (int dy = 0; dy < 3; dy++) {
                const float* wb = s_w + ((dy * 3 + dx) * 16 + ci) * 64 + cout0;
                ulonglong2 w01 = *(const ulonglong2*)(wb);       // couts 0..3
                ulonglong2 w23 = *(const ulonglong2*)(wb + 4);   // couts 4..7
                #pragma unroll
                for (int p = 0; p < 8; p++) {
                    ffma2(acc[p][0], xv[p + dy], w01.x);
                    ffma2(acc[p][1], xv[p + dy], w01.y);
                    ffma2(acc[p][2], xv[p + dy], w23.x);
                    ffma2(acc[p][3], xv[p + dy], w23.y);
                }
            }
        }
    }

    // ---- epilogue: +old, threshold, reset, store both ----
    const int gx = x0 + px;
    #pragma unroll
    for (int p = 0; p < 8; p++) {
        int gy = y0 + py0 + p;
        int base = (gy * WW + gx) * COUT + cout0;
        float4 o0 = *(const float4*)(oldp + base);
        float4 o1 = *(const float4*)(oldp + base + 4);
        float2 a0 = unpack2(acc[p][0]);
        float2 a1 = unpack2(acc[p][1]);
        float2 a2 = unpack2(acc[p][2]);
        float2 a3 = unpack2(acc[p][3]);
        float v0 = a0.x + o0.x, v1 = a0.y + o0.y;
        float v2 = a1.x + o0.z, v3 = a1.y + o0.w;
        float v4 = a2.x + o1.x, v5 = a2.y + o1.y;
        float v6 = a3.x + o1.z, v7 = a3.y + o1.w;
        bool f0 = v0 >= 1.f, f1 = v1 >= 1.f, f2 = v2 >= 1.f, f3 = v3 >= 1.f;
        bool f4 = v4 >= 1.f, f5 = v5 >= 1.f, f6 = v6 >= 1.f, f7 = v7 >= 1.f;
        *(float4*)(out_spk + base) =
            make_float4(f0?1.f:0.f, f1?1.f:0.f, f2?1.f:0.f, f3?1.f:0.f);
        *(float4*)(out_spk + base + 4) =
            make_float4(f4?1.f:0.f, f5?1.f:0.f, f6?1.f:0.f, f7?1.f:0.f);
        *(float4*)(out_pot + base) =
            make_float4(f0?0.f:v0, f1?0.f:v1, f2?0.f:v2, f3?0.f:v3);
        *(float4*)(out_pot + base + 4) =
            make_float4(f4?0.f:v4, f5?0.f:v5, f6?0.f:v6, f7?0.f:v7);
    }
}

extern "C" void kernel_launch(void* const* d_in, const int* in_sizes, int n_in,
                              void* d_out, int out_size) {
    const float* in   = (const float*)d_in[0];   // [1,512,512,16]
    const float* wt   = (const float*)d_in[1];   // [3,3,16,64]
    const float* oldp = (const float*)d_in[2];   // [1,512,512,64]
    float* spk = (float*)d_out;
    float* pot = (float*)d_out + in_sizes[2];

    cudaFuncSetAttribute(snn_conv_kernel,
                         cudaFuncAttributeMaxDynamicSharedMemorySize, SMEM_BYTES);

    dim3 grid(WW / TW, HH / TH);
    snn_conv_kernel<<<grid, 256, SMEM_BYTES>>>(in, wt, oldp, spk, pot);
}

// round 6
// speedup vs baseline: 2.1012x; 1.7451x over previous
#include <cuda_runtime.h>
#include <cuda_fp16.h>
#include <cstdint>

// y = conv2d(x[1,512,512,16], w[3,3,16,64], SAME); pot = y + old
// spike = pot >= 1; new_pot = spike ? 0 : pot
// d_out: [spikes 512*512*64][new_pot 512*512*64]
//
// Implicit GEMM on HMMA (mma.sync m16n8k16 f16, f32 accum).
// fp32 emulated with split-2 fp16 (hi+lo, ~22 mantissa bits), 3 cross products.
// Block tile: 128 x-pixels (one y row) x 64 couts. Warp: 16 px x 64 couts.

#define HH 512
#define WW 512
#define CIN 16
#define COUT 64

#define B_BYTES (9 * 2 * 8 * 32 * 8)   /* 36864: B fragments [tap][s][nt][lane]{2regs} */
#define A_PITCH 48                     /* bytes per pixel-row: 16 ci f16 + pad */
#define A_BUF   (130 * A_PITCH)        /* 6240 per (split,row) buffer */
#define A_OFF   B_BYTES
#define SMEM_TOTAL (A_OFF + 6 * A_BUF) /* 74304 */

// Pre-built B fragments, exact m16n8k16 ".col" lane layout.
__device__ static uint2 g_Bfrag[9 * 2 * 8 * 32];

__device__ __forceinline__ uint32_t smem_u32(const void* p) {
    uint32_t a;
    asm("{ .reg .u64 t; cvta.to.shared.u64 t, %1; cvt.u32.u64 %0, t; }"
        : "=r"(a) : "l"(p));
    return a;
}
__device__ __forceinline__ uint32_t pack_h2(float a, float b) {
    __half2 h = __floats2half2_rn(a, b);
    return *(uint32_t*)&h;
}
__device__ __forceinline__ float h_rt(float v) {   // round-trip through fp16
    return __half2float(__float2half_rn(v));
}
__device__ __forceinline__ void ldmatrix_x4(uint32_t* r, uint32_t addr) {
    asm volatile("ldmatrix.sync.aligned.m8n8.x4.shared.b16 {%0,%1,%2,%3}, [%4];"
                 : "=r"(r[0]), "=r"(r[1]), "=r"(r[2]), "=r"(r[3]) : "r"(addr));
}
__device__ __forceinline__ void mma_f16(float* d, const uint32_t* a, uint2 b) {
    asm volatile(
        "mma.sync.aligned.m16n8k16.row.col.f32.f16.f16.f32 "
        "{%0,%1,%2,%3}, {%4,%5,%6,%7}, {%8,%9}, {%0,%1,%2,%3};"
        : "+f"(d[0]), "+f"(d[1]), "+f"(d[2]), "+f"(d[3])
        : "r"(a[0]), "r"(a[1]), "r"(a[2]), "r"(a[3]), "r"(b.x), "r"(b.y));
}

// ---- prep: build B fragments (hi and lo splits) in mma lane layout ----
__global__ void prep_weights(const float* __restrict__ wt) {
    int idx = blockIdx.x * 256 + threadIdx.x;
    if (idx >= 9 * 2 * 8 * 32) return;
    int lane = idx & 31;
    int t = idx >> 5;
    int nt = t & 7;  t >>= 3;
    int s = t & 1;
    int tap = t >> 1;
    int g = lane >> 2, tg = lane & 3;
    int n = nt * 8 + g;
    float w[4];
    int kk[4] = {tg * 2, tg * 2 + 1, tg * 2 + 8, tg * 2 + 9};
    #pragma unroll
    for (int j = 0; j < 4; j++) {
        float wv = wt[(tap * 16 + kk[j]) * 64 + n];
        w[j] = s == 0 ? wv : (wv - h_rt(wv));
    }
    g_Bfrag[idx] = make_uint2(pack_h2(w[0], w[1]), pack_h2(w[2], w[3]));
}

// ---- main kernel ----
__global__ void __launch_bounds__(256, 2)
snn_conv_mma(const float* __restrict__ in, const float* __restrict__ oldp,
             float* __restrict__ out_spk, float* __restrict__ out_pot) {
    extern __shared__ char smem[];
    const uint32_t sb = smem_u32(smem);
    const int tid = threadIdx.x;
    const int wid = tid >> 5;
    const int lane = tid & 31;
    const int x0 = blockIdx.x * 128;
    const int y  = blockIdx.y;

    // ---- stage B fragments (straight copy) ----
    {
        const uint4* src = (const uint4*)g_Bfrag;
        uint4* dst = (uint4*)smem;
        #pragma unroll
        for (int i = tid; i < B_BYTES / 16; i += 256) dst[i] = src[i];
    }
    // ---- stage A: 3 source rows x 130 px x 16 ci, split hi/lo fp16 ----
    for (int i = tid; i < 3 * 130 * 4; i += 256) {
        int q = i & 3;            // float4 group of 4 ci
        int t = i >> 2;
        int p = t % 130;          // buffer row (gx = x0 + p - 1)
        int r = t / 130;          // source row (gy = y + r - 1)
        int gx = x0 + p - 1, gy = y + r - 1;
        float4 v = make_float4(0.f, 0.f, 0.f, 0.f);
        if ((unsigned)gx < WW && (unsigned)gy < HH)
            v = *(const float4*)(in + (gy * WW + gx) * CIN + q * 4);
        float hx = h_rt(v.x), hy = h_rt(v.y);
        float hz = h_rt(v.z), hw = h_rt(v.w);
        char* rh = smem + A_OFF + r * A_BUF + p * A_PITCH + q * 8;
        char* rl = rh + 3 * A_BUF;
        *(uint32_t*)(rh)     = pack_h2(v.x, v.y);
        *(uint32_t*)(rh + 4) = pack_h2(v.z, v.w);
        *(uint32_t*)(rl)     = pack_h2(v.x - hx, v.y - hy);
        *(uint32_t*)(rl + 4) = pack_h2(v.z - hz, v.w - hw);
    }
    __syncthreads();

    // warp tile: pixels m0..m0+15, all 64 couts
    const int m0 = wid * 16;
    const uint32_t rowsel = (lane & 7) + ((lane >> 3) & 1) * 8;
    const uint32_t koff = (lane >> 4) * 16;

    float acc[8][4];
    #pragma unroll
    for (int nt = 0; nt < 8; nt++)
        #pragma unroll
        for (int j = 0; j < 4; j++) acc[nt][j] = 0.f;

    #pragma unroll 1
    for (int tap = 0; tap < 9; tap++) {
        const int dy = tap / 3, dx = tap - dy * 3;
        uint32_t ah[4], al[4];
        uint32_t aaddr = sb + A_OFF + dy * A_BUF +
                         (m0 + dx + rowsel) * A_PITCH + koff;
        ldmatrix_x4(ah, aaddr);
        ldmatrix_x4(al, aaddr + 3 * A_BUF);

        const char* bb = smem + (tap * 2 * 8 * 32 + lane) * 8;
        uint2 bh[8], bl[8];
        #pragma unroll
        for (int nt = 0; nt < 8; nt++) {
            bh[nt] = *(const uint2*)(bb + nt * 256);
            bl[nt] = *(const uint2*)(bb + nt * 256 + 2048);
        }
        #pragma unroll
        for (int nt = 0; nt < 8; nt++) {
            mma_f16(acc[nt], ah, bh[nt]);   // hi * hi
            mma_f16(acc[nt], ah, bl[nt]);   // hi * lo_w
            mma_f16(acc[nt], al, bh[nt]);   // lo_x * hi
        }
    }

    // ---- epilogue: +old, threshold, reset, store both outputs ----
    const int g = lane >> 2, tg = lane & 3;
    #pragma unroll
    for (int half = 0; half < 2; half++) {
        int m = m0 + g + half * 8;
        int base = (y * WW + x0 + m) * COUT + tg * 2;
        #pragma unroll
        for (int nt = 0; nt < 8; nt++) {
            int off = base + nt * 8;
            float2 o = *(const float2*)(oldp + off);
            float v0 = acc[nt][half * 2 + 0] + o.x;
            float v1 = acc[nt][half * 2 + 1] + o.y;
            bool f0 = v0 >= 1.f, f1 = v1 >= 1.f;
            *(float2*)(out_spk + off) = make_float2(f0 ? 1.f : 0.f, f1 ? 1.f : 0.f);
            *(float2*)(out_pot + off) = make_float2(f0 ? 0.f : v0, f1 ? 0.f : v1);
        }
    }
}

extern "C" void kernel_launch(void* const* d_in, const int* in_sizes, int n_in,
                              void* d_out, int out_size) {
    const float* in   = (const float*)d_in[0];   // [1,512,512,16]
    const float* wt   = (const float*)d_in[1];   // [3,3,16,64]
    const float* oldp = (const float*)d_in[2];   // [1,512,512,64]
    float* spk = (float*)d_out;
    float* pot = (float*)d_out + in_sizes[2];

    prep_weights<<<(9 * 2 * 8 * 32 + 255) / 256, 256>>>(wt);

    cudaFuncSetAttribute(snn_conv_mma,
                         cudaFuncAttributeMaxDynamicSharedMemorySize, SMEM_TOTAL);
    dim3 grid(WW / 128, HH);   // 4 x 512
    snn_conv_mma<<<grid, 256, SMEM_TOTAL>>>(in, oldp, spk, pot);
}

// round 7
// speedup vs baseline: 2.2556x; 1.0735x over previous
#include <cuda_runtime.h>
#include <cuda_fp16.h>
#include <cstdint>

// y = conv2d(x[1,512,512,16], w[3,3,16,64], SAME); pot = y + old
// spike = pot >= 1; new_pot = spike ? 0 : pot
// d_out: [spikes 512*512*64][new_pot 512*512*64]
//
// Implicit GEMM on HMMA (mma.sync m16n8k16 f16, f32 accum).
// fp32 emulated with split-2 fp16 (hi+lo), 3 cross products (hh, h*lw, lx*h).
// Block tile: 128 x-pixels (one y row) x 64 couts. Warp: 16 px x 64 couts.
// 3 CTAs/SM for latency hiding (prev round was latency-bound at occ 2).

#define HH 512
#define WW 512
#define CIN 16
#define COUT 64

#define B_BYTES (9 * 2 * 8 * 32 * 8)   /* 36864: B frags [tap][s][nt][lane]{2regs} */
#define A_PITCH 48                     /* bytes per pixel-row: 16 ci f16 + pad */
#define A_BUF   (130 * A_PITCH)        /* 6240 per (split,row) buffer */
#define A_OFF   B_BYTES
#define SMEM_TOTAL (A_OFF + 6 * A_BUF) /* 74304 ; x3 CTAs = 222912 <= 228KB */

__device__ static uint2 g_Bfrag[9 * 2 * 8 * 32];

__device__ __forceinline__ uint32_t smem_u32(const void* p) {
    uint32_t a;
    asm("{ .reg .u64 t; cvta.to.shared.u64 t, %1; cvt.u32.u64 %0, t; }"
        : "=r"(a) : "l"(p));
    return a;
}
__device__ __forceinline__ uint32_t pack_h2(float a, float b) {
    __half2 h = __floats2half2_rn(a, b);
    return *(uint32_t*)&h;
}
__device__ __forceinline__ float h_rt(float v) {
    return __half2float(__float2half_rn(v));
}
__device__ __forceinline__ void ldmatrix_x4(uint32_t* r, uint32_t addr) {
    asm volatile("ldmatrix.sync.aligned.m8n8.x4.shared.b16 {%0,%1,%2,%3}, [%4];"
                 : "=r"(r[0]), "=r"(r[1]), "=r"(r[2]), "=r"(r[3]) : "r"(addr));
}
__device__ __forceinline__ void mma_f16(float* d, const uint32_t* a, uint2 b) {
    asm volatile(
        "mma.sync.aligned.m16n8k16.row.col.f32.f16.f16.f32 "
        "{%0,%1,%2,%3}, {%4,%5,%6,%7}, {%8,%9}, {%0,%1,%2,%3};"
        : "+f"(d[0]), "+f"(d[1]), "+f"(d[2]), "+f"(d[3])
        : "r"(a[0]), "r"(a[1]), "r"(a[2]), "r"(a[3]), "r"(b.x), "r"(b.y));
}

// ---- prep: build B fragments (hi and lo splits) in mma lane layout ----
__global__ void prep_weights(const float* __restrict__ wt) {
    int idx = blockIdx.x * 256 + threadIdx.x;
    if (idx >= 9 * 2 * 8 * 32) return;
    int lane = idx & 31;
    int t = idx >> 5;
    int nt = t & 7;  t >>= 3;
    int s = t & 1;
    int tap = t >> 1;
    int g = lane >> 2, tg = lane & 3;
    int n = nt * 8 + g;
    float w[4];
    int kk[4] = {tg * 2, tg * 2 + 1, tg * 2 + 8, tg * 2 + 9};
    #pragma unroll
    for (int j = 0; j < 4; j++) {
        float wv = wt[(tap * 16 + kk[j]) * 64 + n];
        w[j] = s == 0 ? wv : (wv - h_rt(wv));
    }
    g_Bfrag[idx] = make_uint2(pack_h2(w[0], w[1]), pack_h2(w[2], w[3]));
}

// ---- main kernel ----
__global__ void __launch_bounds__(256, 3)
snn_conv_mma(const float* __restrict__ in, const float* __restrict__ oldp,
             float* __restrict__ out_spk, float* __restrict__ out_pot) {
    extern __shared__ char smem[];
    const uint32_t sb = smem_u32(smem);
    const int tid = threadIdx.x;
    const int wid = tid >> 5;
    const int lane = tid & 31;
    const int x0 = blockIdx.x * 128;
    const int y  = blockIdx.y;

    // ---- stage B fragments (straight copy) ----
    {
        const uint4* src = (const uint4*)g_Bfrag;
        uint4* dst = (uint4*)smem;
        #pragma unroll
        for (int i = tid; i < B_BYTES / 16; i += 256) dst[i] = src[i];
    }
    // ---- stage A: 3 source rows x 130 px x 16 ci, split hi/lo fp16 ----
    for (int i = tid; i < 3 * 130 * 4; i += 256) {
        int q = i & 3;
        int t = i >> 2;
        int p = t % 130;          // buffer row (gx = x0 + p - 1)
        int r = t / 130;          // source row (gy = y + r - 1)
        int gx = x0 + p - 1, gy = y + r - 1;
        float4 v = make_float4(0.f, 0.f, 0.f, 0.f);
        if ((unsigned)gx < WW && (unsigned)gy < HH)
            v = *(const float4*)(in + (gy * WW + gx) * CIN + q * 4);
        float hx = h_rt(v.x), hy = h_rt(v.y);
        float hz = h_rt(v.z), hw = h_rt(v.w);
        char* rh = smem + A_OFF + r * A_BUF + p * A_PITCH + q * 8;
        char* rl = rh + 3 * A_BUF;
        *(uint32_t*)(rh)     = pack_h2(v.x, v.y);
        *(uint32_t*)(rh + 4) = pack_h2(v.z, v.w);
        *(uint32_t*)(rl)     = pack_h2(v.x - hx, v.y - hy);
        *(uint32_t*)(rl + 4) = pack_h2(v.z - hz, v.w - hw);
    }
    __syncthreads();

    // warp tile: pixels m0..m0+15, all 64 couts
    const int m0 = wid * 16;
    const uint32_t rowsel = (lane & 7) + ((lane >> 3) & 1) * 8;
    const uint32_t koff = (lane >> 4) * 16;

    float acc[8][4];
    #pragma unroll
    for (int nt = 0; nt < 8; nt++)
        #pragma unroll
        for (int j = 0; j < 4; j++) acc[nt][j] = 0.f;

    #pragma unroll
    for (int tap = 0; tap < 9; tap++) {
        const int dy = tap / 3, dx = tap - dy * 3;
        // B loads first: no consumer for ~20 instrs -> overlap with ldmatrix
        const char* bb = smem + (tap * 2 * 8 * 32 + lane) * 8;
        uint2 bh[8], bl[8];
        #pragma unroll
        for (int nt = 0; nt < 8; nt++) {
            bh[nt] = *(const uint2*)(bb + nt * 256);
            bl[nt] = *(const uint2*)(bb + nt * 256 + 2048);
        }
        uint32_t ah[4], al[4];
        uint32_t aaddr = sb + A_OFF + dy * A_BUF +
                         (m0 + dx + rowsel) * A_PITCH + koff;
        ldmatrix_x4(ah, aaddr);
        ldmatrix_x4(al, aaddr + 3 * A_BUF);

        #pragma unroll
        for (int nt = 0; nt < 8; nt++) {
            mma_f16(acc[nt], ah, bh[nt]);   // hi * hi
            mma_f16(acc[nt], ah, bl[nt]);   // hi * lo_w
            mma_f16(acc[nt], al, bh[nt]);   // lo_x * hi
        }
    }

    // ---- epilogue: +old, threshold, reset, store both outputs ----
    const int g = lane >> 2, tg = lane & 3;
    #pragma unroll
    for (int half = 0; half < 2; half++) {
        int m = m0 + g + half * 8;
        int base = (y * WW + x0 + m) * COUT + tg * 2;
        #pragma unroll
        for (int nt = 0; nt < 8; nt++) {
            int off = base + nt * 8;
            float2 o = *(const float2*)(oldp + off);
            float v0 = acc[nt][half * 2 + 0] + o.x;
            float v1 = acc[nt][half * 2 + 1] + o.y;
            bool f0 = v0 >= 1.f, f1 = v1 >= 1.f;
            *(float2*)(out_spk + off) = make_float2(f0 ? 1.f : 0.f, f1 ? 1.f : 0.f);
            *(float2*)(out_pot + off) = make_float2(f0 ? 0.f : v0, f1 ? 0.f : v1);
        }
    }
}

extern "C" void kernel_launch(void* const* d_in, const int* in_sizes, int n_in,
                              void* d_out, int out_size) {
    const float* in   = (const float*)d_in[0];   // [1,512,512,16]
    const float* wt   = (const float*)d_in[1];   // [3,3,16,64]
    const float* oldp = (const float*)d_in[2];   // [1,512,512,64]
    float* spk = (float*)d_out;
    float* pot = (float*)d_out + in_sizes[2];

    prep_weights<<<(9 * 2 * 8 * 32 + 255) / 256, 256>>>(wt);

    cudaFuncSetAttribute(snn_conv_mma,
                         cudaFuncAttributeMaxDynamicSharedMemorySize, SMEM_TOTAL);
    dim3 grid(WW / 128, HH);   // 4 x 512
    snn_conv_mma<<<grid, 256, SMEM_TOTAL>>>(in, oldp, spk, pot);
}